// round 1
// baseline (speedup 1.0000x reference)
#include <cuda_runtime.h>
#include <math.h>

// Problem dims (fixed by setup_inputs)
#define T_TOK 4096          // B*S tokens
#define H_DIM 1024
#define F_DIM 2048
#define E_NUM 8
#define F2    (2 * F_DIM)   // concatenated shared-expert hidden width

// ---------------- scratch (static device globals; no allocs) ----------------
__device__ float g_hid_s[(size_t)T_TOK * F2];          // shared-expert hidden [T, 2F]
__device__ float g_hid_r[(size_t)2 * T_TOK * F_DIM];   // routed hidden, packed by expert
__device__ float g_rout [(size_t)2 * T_TOK * H_DIM];   // routed output, packed by expert
__device__ int   g_counts[E_NUM];
__device__ int   g_base  [E_NUM];
__device__ int   g_list  [E_NUM * T_TOK];              // token ids per expert
__device__ int   g_tok_e   [2 * T_TOK];                // per (token,k): expert id
__device__ int   g_tok_slot[2 * T_TOK];                // per (token,k): slot within expert

// ---------------- router: top-2 of logits (softmax is monotonic) ------------
__global__ void router_kernel(const float* __restrict__ x,
                              const float* __restrict__ rw,
                              const float* __restrict__ rb) {
    int warp = (blockIdx.x * blockDim.x + threadIdx.x) >> 5;
    int lane = threadIdx.x & 31;
    if (warp >= T_TOK) return;
    const float* xp = x + (long)warp * H_DIM;
    float acc[E_NUM];
#pragma unroll
    for (int e = 0; e < E_NUM; e++) acc[e] = 0.f;
    for (int h = lane; h < H_DIM; h += 32) {
        float xv = xp[h];
        const float* w = rw + (long)h * E_NUM;
#pragma unroll
        for (int e = 0; e < E_NUM; e++) acc[e] = fmaf(xv, w[e], acc[e]);
    }
#pragma unroll
    for (int e = 0; e < E_NUM; e++) {
#pragma unroll
        for (int off = 16; off; off >>= 1)
            acc[e] += __shfl_xor_sync(0xFFFFFFFFu, acc[e], off);
    }
    if (lane == 0) {
        float lg[E_NUM];
#pragma unroll
        for (int e = 0; e < E_NUM; e++) lg[e] = acc[e] + rb[e];
        int e0 = 0;
#pragma unroll
        for (int e = 1; e < E_NUM; e++) if (lg[e] > lg[e0]) e0 = e;
        int e1 = -1;
#pragma unroll
        for (int e = 0; e < E_NUM; e++) {
            if (e == e0) continue;
            if (e1 < 0 || lg[e] > lg[e1]) e1 = e;
        }
        int sel[2] = { e0, e1 };
        int t = warp;
#pragma unroll
        for (int k = 0; k < 2; k++) {
            int e = sel[k];
            int slot = atomicAdd(&g_counts[e], 1);
            g_list[e * T_TOK + slot] = t;
            g_tok_e[2 * t + k]    = e;
            g_tok_slot[2 * t + k] = slot;
        }
    }
}

__global__ void base_kernel() {
    if (threadIdx.x == 0) {
        int s = 0;
#pragma unroll
        for (int e = 0; e < E_NUM; e++) { g_base[e] = s; s += g_counts[e]; }
    }
}

// ---------------- generic tiled fp32 GEMM: C = [gelu](A @ W + bias[+bias2]) --
// A: row-major [M, K] (optionally row-gathered), W: row-major [K, N]
#define BM 128
#define BN 128
#define BK 16

template<bool GELU, bool GATHER, bool EXPERT>
__global__ __launch_bounds__(256, 2)
void gemm_kernel(const float* __restrict__ A,
                 const float* __restrict__ W,
                 const float* __restrict__ bias,
                 const float* __restrict__ bias2,
                 float* __restrict__ C,
                 int M, int N, int K, int lda, int ldc,
                 long wStride, int bStride,
                 const int* __restrict__ counts,
                 const int* __restrict__ baseArr,
                 const int* __restrict__ list, int listStride)
{
    __shared__ float As[BK][BM];
    __shared__ float Bs[BK][BN];

    const int* rowidx = nullptr;
    if (EXPERT) {
        int e = blockIdx.z;
        M = counts[e];
        W += (long)e * wStride;
        bias += (long)e * bStride;
        long b = baseArr[e];
        if (GATHER) rowidx = list + (long)e * listStride;
        else        A += b * lda;
        C += b * ldc;
    }
    int rowBase = blockIdx.x * BM;
    if (rowBase >= M) return;
    int colBase = blockIdx.y * BN;

    int tid = threadIdx.x;
    int tx = tid & 15;
    int ty = tid >> 4;

    // A tile loader: each thread loads 8 contiguous K-elements of one row
    int aRow = tid >> 1;
    int aCol = (tid & 1) * 8;
    int gRow = rowBase + aRow;
    bool aValid = gRow < M;
    long aSrc = 0;
    if (GATHER) { if (aValid) aSrc = (long)rowidx[gRow]; }
    else aSrc = gRow;
    const float* aPtr = A + aSrc * lda + aCol;

    // B tile loader: each thread loads 8 contiguous N-elements of one K-row
    int bRow = tid >> 4;
    int bCol = (tid & 15) * 8;
    const float* wPtr = W + (long)bRow * N + colBase + bCol;

    float acc[8][8];
#pragma unroll
    for (int i = 0; i < 8; i++)
#pragma unroll
        for (int j = 0; j < 8; j++) acc[i][j] = 0.f;

    for (int k0 = 0; k0 < K; k0 += BK) {
        float4 a0, a1;
        if (aValid) {
            a0 = *(const float4*)(aPtr + k0);
            a1 = *(const float4*)(aPtr + k0 + 4);
        } else {
            a0 = make_float4(0.f, 0.f, 0.f, 0.f); a1 = a0;
        }
        As[aCol + 0][aRow] = a0.x; As[aCol + 1][aRow] = a0.y;
        As[aCol + 2][aRow] = a0.z; As[aCol + 3][aRow] = a0.w;
        As[aCol + 4][aRow] = a1.x; As[aCol + 5][aRow] = a1.y;
        As[aCol + 6][aRow] = a1.z; As[aCol + 7][aRow] = a1.w;

        const float* wp = wPtr + (long)k0 * N;
        *(float4*)&Bs[bRow][bCol]     = *(const float4*)(wp);
        *(float4*)&Bs[bRow][bCol + 4] = *(const float4*)(wp + 4);

        __syncthreads();
#pragma unroll
        for (int kk = 0; kk < BK; kk++) {
            float a[8], b[8];
            *(float4*)(a)     = *(const float4*)&As[kk][ty * 8];
            *(float4*)(a + 4) = *(const float4*)&As[kk][ty * 8 + 4];
            *(float4*)(b)     = *(const float4*)&Bs[kk][tx * 8];
            *(float4*)(b + 4) = *(const float4*)&Bs[kk][tx * 8 + 4];
#pragma unroll
            for (int i = 0; i < 8; i++)
#pragma unroll
                for (int j = 0; j < 8; j++)
                    acc[i][j] = fmaf(a[i], b[j], acc[i][j]);
        }
        __syncthreads();
    }

    int col = colBase + tx * 8;
    float bv[8];
#pragma unroll
    for (int j = 0; j < 8; j++) {
        float v = bias[col + j];
        if (bias2) v += bias2[col + j];
        bv[j] = v;
    }
#pragma unroll
    for (int i = 0; i < 8; i++) {
        int row = rowBase + ty * 8 + i;
        if (row < M) {
            float outv[8];
#pragma unroll
            for (int j = 0; j < 8; j++) {
                float v = acc[i][j] + bv[j];
                if (GELU) v = 0.5f * v * (1.0f + erff(v * 0.70710678118654752f));
                outv[j] = v;
            }
            float* cp = C + (long)row * ldc + col;
            *(float4*)(cp)     = *(float4*)(outv);
            *(float4*)(cp + 4) = *(float4*)(outv + 4);
        }
    }
}

// ---------------- final combine: out += two routed rows per token ------------
__global__ void combine_kernel(float* __restrict__ out) {
    int t = blockIdx.x;
    int e0 = g_tok_e[2 * t], e1 = g_tok_e[2 * t + 1];
    long r0 = (long)g_base[e0] + g_tok_slot[2 * t];
    long r1 = (long)g_base[e1] + g_tok_slot[2 * t + 1];
    const float4* p0 = (const float4*)g_rout + r0 * (H_DIM / 4);
    const float4* p1 = (const float4*)g_rout + r1 * (H_DIM / 4);
    float4* op = (float4*)out + (long)t * (H_DIM / 4);
    int i = threadIdx.x;   // 256 threads == H/4
    float4 o = op[i], a = p0[i], b = p1[i];
    o.x += a.x + b.x; o.y += a.y + b.y;
    o.z += a.z + b.z; o.w += a.w + b.w;
    op[i] = o;
}

// ---------------- launch ----------------
extern "C" void kernel_launch(void* const* d_in, const int* in_sizes, int n_in,
                              void* d_out, int out_size)
{
    const float* x   = (const float*)d_in[0];
    const float* sw1 = (const float*)d_in[1];
    const float* sb1 = (const float*)d_in[2];
    const float* sw2 = (const float*)d_in[3];
    const float* sb2 = (const float*)d_in[4];
    const float* ew1 = (const float*)d_in[5];
    const float* eb1 = (const float*)d_in[6];
    const float* ew2 = (const float*)d_in[7];
    const float* eb2 = (const float*)d_in[8];
    const float* rw  = (const float*)d_in[9];
    const float* rb  = (const float*)d_in[10];
    float* out = (float*)d_out;

    float *hid_s, *hid_r, *rout;
    int *counts, *baseArr, *list;
    cudaGetSymbolAddress((void**)&hid_s,  g_hid_s);
    cudaGetSymbolAddress((void**)&hid_r,  g_hid_r);
    cudaGetSymbolAddress((void**)&rout,   g_rout);
    cudaGetSymbolAddress((void**)&counts, g_counts);
    cudaGetSymbolAddress((void**)&baseArr,g_base);
    cudaGetSymbolAddress((void**)&list,   g_list);

    cudaMemsetAsync(counts, 0, E_NUM * sizeof(int));

    router_kernel<<<T_TOK / 4, 128>>>(x, rw, rb);
    base_kernel<<<1, 32>>>();

    dim3 blk(256);

    // shared GEMM1 (x2): hid_s[:, n*F : (n+1)*F] = gelu(x @ sw1[n] + sb1[n])
    for (int n = 0; n < 2; n++) {
        gemm_kernel<true, false, false><<<dim3(T_TOK / BM, F_DIM / BN, 1), blk>>>(
            x, sw1 + (long)n * H_DIM * F_DIM, sb1 + n * F_DIM, nullptr,
            hid_s + n * F_DIM,
            T_TOK, F_DIM, H_DIM, H_DIM, F2,
            0, 0, nullptr, nullptr, nullptr, 0);
    }

    // routed GEMM1: per expert, gather token rows of x
    gemm_kernel<true, true, true><<<dim3(T_TOK / BM, F_DIM / BN, E_NUM), blk>>>(
        x, ew1, eb1, nullptr, hid_r,
        0, F_DIM, H_DIM, H_DIM, F_DIM,
        (long)H_DIM * F_DIM, F_DIM, counts, baseArr, list, T_TOK);

    // shared GEMM2: out = hid_s @ [sw2_0; sw2_1] + (sb2_0 + sb2_1)
    gemm_kernel<false, false, false><<<dim3(T_TOK / BM, H_DIM / BN, 1), blk>>>(
        hid_s, sw2, sb2, sb2 + H_DIM,
        out, T_TOK, H_DIM, F2, F2, H_DIM,
        0, 0, nullptr, nullptr, nullptr, 0);

    // routed GEMM2: rout rows = hid_r rows @ ew2[e] + eb2[e]
    gemm_kernel<false, false, true><<<dim3(T_TOK / BM, H_DIM / BN, E_NUM), blk>>>(
        hid_r, ew2, eb2, nullptr, rout,
        0, H_DIM, F_DIM, F_DIM, H_DIM,
        (long)F_DIM * H_DIM, H_DIM, counts, baseArr, nullptr, 0);

    combine_kernel<<<T_TOK, 256>>>(out);
}

// round 3
// speedup vs baseline: 2.8086x; 2.8086x over previous
#include <cuda_runtime.h>
#include <cuda_bf16.h>
#include <cstdint>
#include <math.h>

#define T_TOK 4096
#define H_DIM 1024
#define F_DIM 2048
#define E_NUM 8
#define F2    (2 * F_DIM)

// ===================== helpers =====================
__device__ __forceinline__ uint32_t smem_u32(const void* p) {
    uint32_t a;
    asm("{ .reg .u64 t; cvta.to.shared.u64 t, %1; cvt.u32.u64 %0, t; }" : "=r"(a) : "l"(p));
    return a;
}
#define SW128(off) ((off) ^ (((off) >> 3) & 0x70))

__device__ __forceinline__ void cp_async16(uint32_t dst, const void* src, int srcBytes) {
    asm volatile("cp.async.cg.shared.global [%0], [%1], 16, %2;"
                 :: "r"(dst), "l"(src), "r"(srcBytes) : "memory");
}
#define CP_COMMIT() asm volatile("cp.async.commit_group;" ::: "memory")
#define CP_WAIT(n)  asm volatile("cp.async.wait_group %0;" :: "n"(n) : "memory")

__device__ __forceinline__ void ldsm4(uint32_t* r, uint32_t addr) {
    asm volatile("ldmatrix.sync.aligned.m8n8.x4.shared.b16 {%0,%1,%2,%3}, [%4];"
                 : "=r"(r[0]), "=r"(r[1]), "=r"(r[2]), "=r"(r[3]) : "r"(addr));
}

__device__ __forceinline__ void mma16816(float* d, const uint32_t* a, uint32_t b0, uint32_t b1) {
    asm volatile("mma.sync.aligned.m16n8k16.row.col.f32.bf16.bf16.f32 "
                 "{%0,%1,%2,%3}, {%4,%5,%6,%7}, {%8,%9}, {%0,%1,%2,%3};"
                 : "+f"(d[0]), "+f"(d[1]), "+f"(d[2]), "+f"(d[3])
                 : "r"(a[0]), "r"(a[1]), "r"(a[2]), "r"(a[3]), "r"(b0), "r"(b1));
}

__device__ __forceinline__ uint32_t pack_bf16(float x, float y) {
    __nv_bfloat162 t;
    t.x = __float2bfloat16(x);
    t.y = __float2bfloat16(y);
    return *(uint32_t*)&t;
}

// ===================== scratch (device globals; no allocs) =====================
__device__ __nv_bfloat16 g_x_hi [(size_t)T_TOK * H_DIM];
__device__ __nv_bfloat16 g_x_lo [(size_t)T_TOK * H_DIM];
__device__ __nv_bfloat16 g_sw1t_hi[(size_t)2 * F_DIM * H_DIM];
__device__ __nv_bfloat16 g_sw1t_lo[(size_t)2 * F_DIM * H_DIM];
__device__ __nv_bfloat16 g_ew1t_hi[(size_t)E_NUM * F_DIM * H_DIM];
__device__ __nv_bfloat16 g_ew1t_lo[(size_t)E_NUM * F_DIM * H_DIM];
__device__ __nv_bfloat16 g_sw2t_hi[(size_t)H_DIM * F2];
__device__ __nv_bfloat16 g_sw2t_lo[(size_t)H_DIM * F2];
__device__ __nv_bfloat16 g_ew2t_hi[(size_t)E_NUM * H_DIM * F_DIM];
__device__ __nv_bfloat16 g_ew2t_lo[(size_t)E_NUM * H_DIM * F_DIM];
__device__ __nv_bfloat16 g_hids_hi[(size_t)T_TOK * F2];
__device__ __nv_bfloat16 g_hids_lo[(size_t)T_TOK * F2];
__device__ __nv_bfloat16 g_hidr_hi[(size_t)2 * T_TOK * F_DIM];
__device__ __nv_bfloat16 g_hidr_lo[(size_t)2 * T_TOK * F_DIM];
__device__ float g_rout[(size_t)2 * T_TOK * H_DIM];
__device__ int g_counts[E_NUM];
__device__ int g_base[E_NUM];
__device__ int g_list[E_NUM * T_TOK];
__device__ int g_tok_e[2 * T_TOK];
__device__ int g_tok_slot[2 * T_TOK];

// ===================== router / base / combine =====================
__global__ void router_kernel(const float* __restrict__ x,
                              const float* __restrict__ rw,
                              const float* __restrict__ rb) {
    int warp = (blockIdx.x * blockDim.x + threadIdx.x) >> 5;
    int lane = threadIdx.x & 31;
    if (warp >= T_TOK) return;
    const float* xp = x + (long)warp * H_DIM;
    float acc[E_NUM];
#pragma unroll
    for (int e = 0; e < E_NUM; e++) acc[e] = 0.f;
    for (int h = lane; h < H_DIM; h += 32) {
        float xv = xp[h];
        const float* w = rw + (long)h * E_NUM;
#pragma unroll
        for (int e = 0; e < E_NUM; e++) acc[e] = fmaf(xv, w[e], acc[e]);
    }
#pragma unroll
    for (int e = 0; e < E_NUM; e++)
#pragma unroll
        for (int off = 16; off; off >>= 1)
            acc[e] += __shfl_xor_sync(0xFFFFFFFFu, acc[e], off);
    if (lane == 0) {
        float lg[E_NUM];
#pragma unroll
        for (int e = 0; e < E_NUM; e++) lg[e] = acc[e] + rb[e];
        int e0 = 0;
#pragma unroll
        for (int e = 1; e < E_NUM; e++) if (lg[e] > lg[e0]) e0 = e;
        int e1 = -1;
#pragma unroll
        for (int e = 0; e < E_NUM; e++) {
            if (e == e0) continue;
            if (e1 < 0 || lg[e] > lg[e1]) e1 = e;
        }
        int sel[2] = { e0, e1 };
        int t = warp;
#pragma unroll
        for (int k = 0; k < 2; k++) {
            int e = sel[k];
            int slot = atomicAdd(&g_counts[e], 1);
            g_list[e * T_TOK + slot] = t;
            g_tok_e[2 * t + k] = e;
            g_tok_slot[2 * t + k] = slot;
        }
    }
}

__global__ void base_kernel() {
    if (threadIdx.x == 0) {
        int s = 0;
#pragma unroll
        for (int e = 0; e < E_NUM; e++) { g_base[e] = s; s += g_counts[e]; }
    }
}

__global__ void combine_kernel(float* __restrict__ out) {
    int t = blockIdx.x;
    int e0 = g_tok_e[2 * t], e1 = g_tok_e[2 * t + 1];
    long r0 = (long)g_base[e0] + g_tok_slot[2 * t];
    long r1 = (long)g_base[e1] + g_tok_slot[2 * t + 1];
    const float4* p0 = (const float4*)g_rout + r0 * (H_DIM / 4);
    const float4* p1 = (const float4*)g_rout + r1 * (H_DIM / 4);
    float4* op = (float4*)out + (long)t * (H_DIM / 4);
    int i = threadIdx.x;
    float4 o = op[i], a = p0[i], b = p1[i];
    o.x += a.x + b.x; o.y += a.y + b.y; o.z += a.z + b.z; o.w += a.w + b.w;
    op[i] = o;
}

// ===================== fp32 -> bf16 hi/lo converters =====================
__global__ void split_kernel(const float* __restrict__ in,
                             __nv_bfloat16* __restrict__ hi,
                             __nv_bfloat16* __restrict__ lo, int n4) {
    int i = blockIdx.x * blockDim.x + threadIdx.x;
    if (i >= n4) return;
    float4 v = ((const float4*)in)[i];
    union { __nv_bfloat16 b[4]; uint2 u; } hb, lb;
    float vv[4] = { v.x, v.y, v.z, v.w };
#pragma unroll
    for (int u = 0; u < 4; u++) {
        __nv_bfloat16 h = __float2bfloat16(vv[u]);
        hb.b[u] = h;
        lb.b[u] = __float2bfloat16(vv[u] - __bfloat162float(h));
    }
    ((uint2*)hi)[i] = hb.u;
    ((uint2*)lo)[i] = lb.u;
}

// transpose + split: in [E][K][N] -> hi/lo at e*outEStride + n*ldOut + e*colOffE + k
__global__ void tsplit_kernel(const float* __restrict__ in,
                              __nv_bfloat16* __restrict__ hi,
                              __nv_bfloat16* __restrict__ lo,
                              int K, int N, long outEStride, int ldOut, int colOffE) {
    __shared__ float t[32][33];
    int e = blockIdx.z;
    int n0 = blockIdx.x * 32, k0 = blockIdx.y * 32;
    const float* src = in + (long)e * K * N;
    int tx = threadIdx.x, ty = threadIdx.y;
#pragma unroll
    for (int i = 0; i < 32; i += 8)
        t[ty + i][tx] = src[(long)(k0 + ty + i) * N + n0 + tx];
    __syncthreads();
    long obase = (long)e * outEStride + (long)e * colOffE;
#pragma unroll
    for (int i = 0; i < 32; i += 8) {
        float v = t[tx][ty + i];
        __nv_bfloat16 h = __float2bfloat16(v);
        long o = obase + (long)(n0 + ty + i) * ldOut + k0 + tx;
        hi[o] = h;
        lo[o] = __float2bfloat16(v - __bfloat162float(h));
    }
}

// ===================== mma.sync bf16x3 GEMM =====================
// C[M,N] = epi(sum_Kext A_ext @ B_ext^T + bias), tile 128x128, BK=64.
// A: [M,K] hi/lo K-major; B: [N,K] hi/lo K-major (pre-transposed weights).
#define DSMEM_BYTES 65536

template<bool GELU, bool GATHER, bool EXPERT>
__global__ __launch_bounds__(256, 2)
void mma_gemm(const __nv_bfloat16* __restrict__ Ahi_,
              const __nv_bfloat16* __restrict__ Alo_,
              const __nv_bfloat16* __restrict__ Bhi_,
              const __nv_bfloat16* __restrict__ Blo_,
              const float* __restrict__ bias_,
              const float* __restrict__ bias2,
              __nv_bfloat16* __restrict__ Chi_,
              __nv_bfloat16* __restrict__ Clo_,
              float* __restrict__ Cf_,
              int M, int K, int ldc, long wStride, int bStride, int colOffZ)
{
    int z = blockIdx.z;
    const __nv_bfloat16* Bhi = Bhi_ + (long)z * wStride;
    const __nv_bfloat16* Blo = Blo_ + (long)z * wStride;
    const float* bias = bias_ + (long)z * bStride;
    int colOff = colOffZ * z;
    const __nv_bfloat16* Ahi = Ahi_;
    const __nv_bfloat16* Alo = Alo_;
    __nv_bfloat16* Chi = Chi_;
    __nv_bfloat16* Clo = Clo_;
    float* Cf = Cf_;
    const int* list = nullptr;
    if (EXPERT) {
        M = g_counts[z];
        long b = g_base[z];
        if (GATHER) list = g_list + (long)z * T_TOK;
        else { Ahi += b * (long)K; Alo += b * (long)K; }
        if (GELU) { Chi += b * (long)ldc; Clo += b * (long)ldc; }
        else Cf += b * (long)ldc;
    }
    int rowBase = blockIdx.x * 128;
    if (rowBase >= M) return;
    int colBase = blockIdx.y * 128;

    extern __shared__ char smem[];
    uint32_t sbase = smem_u32(smem);
    // layout: [buf0: A 16K | B 16K][buf1: A 16K | B 16K]

    int tid = threadIdx.x;
    int wid = tid >> 5, lane = tid & 31;
    int warpM = wid & 3, warpN = wid >> 2;

    // loader metadata: 4 16B units each for A and B per chunk
    uint32_t swoff[4]; int aRow[4], bRow[4], kel[4]; int aBytes[4];
#pragma unroll
    for (int i = 0; i < 4; i++) {
        int id = tid + i * 256;
        int r = id >> 3, c16 = (id & 7) * 16;
        swoff[i] = SW128((uint32_t)(r * 128 + c16));
        kel[i] = c16 >> 1;               // element offset within 64-wide chunk
        int gR = rowBase + r;
        bool ok = gR < M;
        aBytes[i] = ok ? 16 : 0;
        aRow[i] = GATHER ? (ok ? list[gR] : 0) : (ok ? gR : 0);
        bRow[i] = colBase + r;
    }

    const int kc = K >> 6;
    const int NC = 3 * kc;

    auto issue = [&](int ci) {
        int buf = ci & 1;
        int seg = (ci >= 2 * kc) ? 2 : (ci >= kc ? 1 : 0);
        int kbase = (ci - seg * kc) << 6;
        const __nv_bfloat16* Ap = (seg < 2) ? Ahi : Alo;
        const __nv_bfloat16* Bp = (seg == 1) ? Blo : Bhi;
        uint32_t sA = sbase + buf * 32768;
        uint32_t sB = sA + 16384;
#pragma unroll
        for (int i = 0; i < 4; i++) {
            cp_async16(sA + swoff[i], Ap + (long)aRow[i] * K + kbase + kel[i], aBytes[i]);
            cp_async16(sB + swoff[i], Bp + (long)bRow[i] * K + kbase + kel[i], 16);
        }
        CP_COMMIT();
    };

    float acc[2][8][4];
#pragma unroll
    for (int mi = 0; mi < 2; mi++)
#pragma unroll
        for (int nj = 0; nj < 8; nj++)
#pragma unroll
            for (int u = 0; u < 4; u++) acc[mi][nj][u] = 0.f;

    // precomputed ldmatrix row/col-within-tile for this lane
    int lrow = lane & 15;
    int lc16 = (lane >> 4) * 16;

    issue(0);
    for (int ci = 0; ci < NC; ci++) {
        if (ci + 1 < NC) { issue(ci + 1); CP_WAIT(1); }
        else             { CP_WAIT(0); }
        __syncthreads();
        int buf = ci & 1;
        uint32_t sA = sbase + buf * 32768;
        uint32_t sB = sA + 16384;
#pragma unroll
        for (int ks = 0; ks < 4; ks++) {
            uint32_t a[2][4];
#pragma unroll
            for (int mi = 0; mi < 2; mi++)
                ldsm4(a[mi], sA + SW128((uint32_t)((warpM * 32 + mi * 16 + lrow) * 128 + ks * 32 + lc16)));
            uint32_t b[4][4];
#pragma unroll
            for (int g = 0; g < 4; g++)
                ldsm4(b[g], sB + SW128((uint32_t)((warpN * 64 + g * 16 + lrow) * 128 + ks * 32 + lc16)));
#pragma unroll
            for (int mi = 0; mi < 2; mi++)
#pragma unroll
                for (int g = 0; g < 4; g++) {
                    mma16816(acc[mi][2 * g + 0], a[mi], b[g][0], b[g][2]);
                    mma16816(acc[mi][2 * g + 1], a[mi], b[g][1], b[g][3]);
                }
        }
        __syncthreads();
    }

    // ---------------- epilogue ----------------
    int rw0 = rowBase + warpM * 32 + (lane >> 2);
    int cw0 = colBase + warpN * 64 + (lane & 3) * 2;
#pragma unroll
    for (int mi = 0; mi < 2; mi++) {
#pragma unroll
        for (int nj = 0; nj < 8; nj++) {
            int col = cw0 + nj * 8;
            float b0 = bias[col], b1 = bias[col + 1];
            if (bias2) { b0 += bias2[col]; b1 += bias2[col + 1]; }
#pragma unroll
            for (int h = 0; h < 2; h++) {
                int row = rw0 + mi * 16 + h * 8;
                if (row < M) {
                    float v0 = acc[mi][nj][2 * h + 0] + b0;
                    float v1 = acc[mi][nj][2 * h + 1] + b1;
                    long off = (long)row * ldc + colOff + col;
                    if (GELU) {
                        float g0 = 0.5f * v0 * (1.0f + erff(v0 * 0.70710678118654752f));
                        float g1 = 0.5f * v1 * (1.0f + erff(v1 * 0.70710678118654752f));
                        float h0 = __bfloat162float(__float2bfloat16(g0));
                        float h1 = __bfloat162float(__float2bfloat16(g1));
                        *(uint32_t*)(Chi + off) = pack_bf16(g0, g1);
                        *(uint32_t*)(Clo + off) = pack_bf16(g0 - h0, g1 - h1);
                    } else {
                        float2 v; v.x = v0; v.y = v1;
                        *(float2*)(Cf + off) = v;
                    }
                }
            }
        }
    }
}

// ===================== launch =====================
static void* symAddr(const void* sym) { void* p; cudaGetSymbolAddress(&p, sym); return p; }

extern "C" void kernel_launch(void* const* d_in, const int* in_sizes, int n_in,
                              void* d_out, int out_size)
{
    const float* x   = (const float*)d_in[0];
    const float* sw1 = (const float*)d_in[1];
    const float* sb1 = (const float*)d_in[2];
    const float* sw2 = (const float*)d_in[3];
    const float* sb2 = (const float*)d_in[4];
    const float* ew1 = (const float*)d_in[5];
    const float* eb1 = (const float*)d_in[6];
    const float* ew2 = (const float*)d_in[7];
    const float* eb2 = (const float*)d_in[8];
    const float* rw  = (const float*)d_in[9];
    const float* rb  = (const float*)d_in[10];
    float* out = (float*)d_out;

    __nv_bfloat16* x_hi   = (__nv_bfloat16*)symAddr(g_x_hi);
    __nv_bfloat16* x_lo   = (__nv_bfloat16*)symAddr(g_x_lo);
    __nv_bfloat16* sw1t_h = (__nv_bfloat16*)symAddr(g_sw1t_hi);
    __nv_bfloat16* sw1t_l = (__nv_bfloat16*)symAddr(g_sw1t_lo);
    __nv_bfloat16* ew1t_h = (__nv_bfloat16*)symAddr(g_ew1t_hi);
    __nv_bfloat16* ew1t_l = (__nv_bfloat16*)symAddr(g_ew1t_lo);
    __nv_bfloat16* sw2t_h = (__nv_bfloat16*)symAddr(g_sw2t_hi);
    __nv_bfloat16* sw2t_l = (__nv_bfloat16*)symAddr(g_sw2t_lo);
    __nv_bfloat16* ew2t_h = (__nv_bfloat16*)symAddr(g_ew2t_hi);
    __nv_bfloat16* ew2t_l = (__nv_bfloat16*)symAddr(g_ew2t_lo);
    __nv_bfloat16* hids_h = (__nv_bfloat16*)symAddr(g_hids_hi);
    __nv_bfloat16* hids_l = (__nv_bfloat16*)symAddr(g_hids_lo);
    __nv_bfloat16* hidr_h = (__nv_bfloat16*)symAddr(g_hidr_hi);
    __nv_bfloat16* hidr_l = (__nv_bfloat16*)symAddr(g_hidr_lo);
    float* rout = (float*)symAddr(g_rout);
    int* counts = (int*)symAddr(g_counts);

    cudaFuncSetAttribute(mma_gemm<true, false, false>, cudaFuncAttributeMaxDynamicSharedMemorySize, DSMEM_BYTES);
    cudaFuncSetAttribute(mma_gemm<true, true,  true>,  cudaFuncAttributeMaxDynamicSharedMemorySize, DSMEM_BYTES);
    cudaFuncSetAttribute(mma_gemm<false, false, false>, cudaFuncAttributeMaxDynamicSharedMemorySize, DSMEM_BYTES);
    cudaFuncSetAttribute(mma_gemm<false, false, true>, cudaFuncAttributeMaxDynamicSharedMemorySize, DSMEM_BYTES);

    cudaMemsetAsync(counts, 0, E_NUM * sizeof(int));
    router_kernel<<<T_TOK / 4, 128>>>(x, rw, rb);
    base_kernel<<<1, 32>>>();

    // conversions
    split_kernel<<<(T_TOK * H_DIM / 4 + 255) / 256, 256>>>(x, x_hi, x_lo, T_TOK * H_DIM / 4);
    tsplit_kernel<<<dim3(F_DIM / 32, H_DIM / 32, 2), dim3(32, 8)>>>(
        sw1, sw1t_h, sw1t_l, H_DIM, F_DIM, (long)F_DIM * H_DIM, H_DIM, 0);
    tsplit_kernel<<<dim3(F_DIM / 32, H_DIM / 32, E_NUM), dim3(32, 8)>>>(
        ew1, ew1t_h, ew1t_l, H_DIM, F_DIM, (long)F_DIM * H_DIM, H_DIM, 0);
    tsplit_kernel<<<dim3(H_DIM / 32, F_DIM / 32, 2), dim3(32, 8)>>>(
        sw2, sw2t_h, sw2t_l, F_DIM, H_DIM, 0, F2, F_DIM);
    tsplit_kernel<<<dim3(H_DIM / 32, F_DIM / 32, E_NUM), dim3(32, 8)>>>(
        ew2, ew2t_h, ew2t_l, F_DIM, H_DIM, (long)H_DIM * F_DIM, F_DIM, 0);

    // shared GEMM1: hid_s[:, z*F:(z+1)*F] = gelu(x @ sw1[z] + sb1[z])
    mma_gemm<true, false, false><<<dim3(T_TOK / 128, F_DIM / 128, 2), 256, DSMEM_BYTES>>>(
        x_hi, x_lo, sw1t_h, sw1t_l, sb1, nullptr, hids_h, hids_l, nullptr,
        T_TOK, H_DIM, F2, (long)F_DIM * H_DIM, F_DIM, F_DIM);

    // routed GEMM1: per-expert gathered rows of x
    mma_gemm<true, true, true><<<dim3(T_TOK / 128, F_DIM / 128, E_NUM), 256, DSMEM_BYTES>>>(
        x_hi, x_lo, ew1t_h, ew1t_l, eb1, nullptr, hidr_h, hidr_l, nullptr,
        0, H_DIM, F_DIM, (long)F_DIM * H_DIM, F_DIM, 0);

    // shared GEMM2: out = hid_s @ [sw2_0; sw2_1] + sb2_0 + sb2_1
    mma_gemm<false, false, false><<<dim3(T_TOK / 128, H_DIM / 128, 1), 256, DSMEM_BYTES>>>(
        hids_h, hids_l, sw2t_h, sw2t_l, sb2, sb2 + H_DIM, nullptr, nullptr, out,
        T_TOK, F2, H_DIM, 0, 0, 0);

    // routed GEMM2: rout = hid_r @ ew2[e] + eb2[e]
    mma_gemm<false, false, true><<<dim3(T_TOK / 128, H_DIM / 128, E_NUM), 256, DSMEM_BYTES>>>(
        hidr_h, hidr_l, ew2t_h, ew2t_l, eb2, nullptr, nullptr, nullptr, rout,
        0, F_DIM, H_DIM, (long)H_DIM * F_DIM, H_DIM, 0);

    combine_kernel<<<T_TOK, 256>>>(out);
}